// round 14
// baseline (speedup 1.0000x reference)
#include <cuda_runtime.h>
#include <cstdint>

// WindowAttention3D fused TF32 mma.sync kernel (one CTA per window).
// B=4096 windows, N=98 tokens (pad 112), C=96, H=3 heads, hd=32.
// R13: weight fragments staged in SMEM per matrix (kills redundant weight
// L2 stream); keeps R12 fragment-order operands + in-register attention.

#define N_TOK 98
#define C_DIM 96
#define NHEAD 3
#define HD    32
#define NWIN  4096
#define MPAD  112          // 7 x m16 tiles
#define SLD   100          // q_s / k_s row stride
#define PLD   108          // P (x) row stride
#define VLD   108          // vT row stride

#define NTHREADS 512
#define NW       16

// SMEM float offsets
#define Q_OFF 0                          // 112*100 = 11200   (q, later y)
#define K_OFF 11200                      // 104*100 = 10400
#define V_OFF 21600                      // 3*32*108 = 10368  (vT[h][d][token])
#define P_OFF 31968                      // 112*108 = 12096   (x)
#define W_OFF 44064                      // 12*12*32 float2 = 9216 floats
#define SMEM_FLOATS (44064 + 9216)
#define SMEM_BYTES  (SMEM_FLOATS * 4)    // 213120 B (< 227 KB cap)

// Fragment-order operand caches (prep kernels fill; L2-resident).
// qkv weight B-frags: [mat=3][nt=12][kt=12][lane=32] float2
__device__ float2 g_qkv_wf[36 * 12 * 32];
// proj weight B-frags: [nt=12][kt=12][lane=32] float2
__device__ float2 g_proj_wf[12 * 12 * 32];
// bias C-frags with column mask: [h=3][mt=7][nt=13][lane=32]
__device__ float4 g_bias_f[NHEAD * 7 * 13 * 32];

__device__ __forceinline__ uint32_t f2tf(float f) {
    uint32_t r;
    asm("cvt.rna.tf32.f32 %0, %1;" : "=r"(r) : "f"(f));
    return r;
}
__device__ __forceinline__ float f2tff(float f) { return __uint_as_float(f2tf(f)); }
__device__ __forceinline__ uint32_t fu(float f) { return __float_as_uint(f); }

__global__ void weight_prep_kernel(const float* __restrict__ qkv_w,
                                   const float* __restrict__ proj_w) {
    int i = blockIdx.x * blockDim.x + threadIdx.x;
    const int QKV_N = 36 * 12 * 32;
    if (i < QKV_N) {
        int lane = i & 31, kt = (i >> 5) % 12, nt = i / (32 * 12);
        int gid = lane >> 2, tig = lane & 3;
        int row = nt * 8 + gid, k = kt * 8 + tig;
        g_qkv_wf[i] = make_float2(f2tff(qkv_w[row * C_DIM + k]),
                                  f2tff(qkv_w[row * C_DIM + k + 4]));
    } else if (i < QKV_N + 12 * 12 * 32) {
        int j = i - QKV_N;
        int lane = j & 31, kt = (j >> 5) % 12, nt = j / (32 * 12);
        int gid = lane >> 2, tig = lane & 3;
        int row = nt * 8 + gid, k = kt * 8 + tig;
        g_proj_wf[j] = make_float2(f2tff(proj_w[row * C_DIM + k]),
                                   f2tff(proj_w[row * C_DIM + k + 4]));
    }
}

__global__ void bias_prep_kernel(const float* __restrict__ table,
                                 const int* __restrict__ ridx) {
    int i = blockIdx.x * blockDim.x + threadIdx.x;
    if (i < NHEAD * 7 * 13 * 32) {
        int lane = i & 31;
        int nt   = (i >> 5) % 13;
        int mt   = (i / (32 * 13)) % 7;
        int h    = i / (32 * 13 * 7);
        int gid = lane >> 2, tig = lane & 3;
        int r0 = mt * 16 + gid, r1 = r0 + 8;
        int c0 = nt * 8 + tig * 2;
        auto bv = [&](int r, int c) -> float {
            if (c >= N_TOK) return -1e30f;                    // column mask
            if (r >= N_TOK) return 0.f;                       // padded row
            return table[ridx[r * N_TOK + c] * NHEAD + h];
        };
        g_bias_f[i] = make_float4(bv(r0, c0), bv(r0, c0 + 1),
                                  bv(r1, c0), bv(r1, c0 + 1));
    }
}

__device__ __forceinline__ void mma8(float c[4],
                                     uint32_t a0, uint32_t a1, uint32_t a2, uint32_t a3,
                                     uint32_t b0, uint32_t b1) {
    asm volatile(
        "mma.sync.aligned.m16n8k8.row.col.f32.tf32.tf32.f32 "
        "{%0,%1,%2,%3}, {%4,%5,%6,%7}, {%8,%9}, {%0,%1,%2,%3};"
        : "+f"(c[0]), "+f"(c[1]), "+f"(c[2]), "+f"(c[3])
        : "r"(a0), "r"(a1), "r"(a2), "r"(a3), "r"(b0), "r"(b1));
}

__global__ void __launch_bounds__(NTHREADS, 1)
win_attn_kernel(const float* __restrict__ x,
                const float* __restrict__ qkv_b,   // [288]
                const float* __restrict__ proj_b,  // [96]
                float* __restrict__ out) {
    extern __shared__ float sm[];
    float* q_s = sm + Q_OFF;   // [112][SLD] q*scale, later y (per-(h,mt) private)
    float* k_s = sm + K_OFF;   // [104][SLD] k
    float* vT  = sm + V_OFF;   // [3][32][VLD] v transposed: [h][d][token]
    float* P   = sm + P_OFF;   // [112][PLD] x (TF32-rounded)
    float2* w_s = (float2*)(sm + W_OFF);  // [12 nt][12 kt][32 lane] weight frags

    const int tid  = threadIdx.x;
    const int lane = tid & 31;
    const int warp = tid >> 5;
    const int gid  = lane >> 2;   // groupID 0..7
    const int tig  = lane & 3;    // thread-in-group 0..3
    const int b    = blockIdx.x;
    const float* xb = x + (size_t)b * (N_TOK * C_DIM);

    // ---- Phase 0: load x -> P (TF32-rounded, float4), zero pad rows --------
    for (int i = tid * 4; i < N_TOK * C_DIM; i += NTHREADS * 4) {
        float4 v = *(const float4*)(xb + i);
        int n = i / C_DIM, c = i % C_DIM;
        float4 r = make_float4(f2tff(v.x), f2tff(v.y), f2tff(v.z), f2tff(v.w));
        *(float4*)(P + n * PLD + c) = r;
    }
    for (int i = tid; i < (MPAD - N_TOK) * C_DIM; i += NTHREADS) {
        int n = N_TOK + i / C_DIM, c = i % C_DIM;
        P[n * PLD + c] = 0.f;
    }
    __syncthreads();

    const float scale = 0.17677669529663687f;   // 32^-0.5

    // ---- Phase 1: QKV GEMM per matrix, weights staged in SMEM --------------
    for (int mat = 0; mat < 3; ++mat) {
        // stage this matrix's weight fragments (4608 float2 = 36.9 KB)
        {
            const float2* src = g_qkv_wf + mat * (12 * 12 * 32);
            for (int i = tid; i < 12 * 12 * 32; i += NTHREADS)
                w_s[i] = src[i];
        }
        __syncthreads();

        // task = (m-tile, n-half of 6 tiles): 14 tasks
        for (int t = warp; t < 14; t += NW) {
            const int mt = t >> 1;
            const int nh = t & 1;
            // cache A fragments for this m-tile (x)
            uint32_t ax[12][4];
            const float* ab0 = P + (mt * 16 + gid) * PLD + tig;
            #pragma unroll
            for (int kt = 0; kt < 12; ++kt) {
                const int kc = kt * 8;
                ax[kt][0] = fu(ab0[kc]);
                ax[kt][1] = fu(ab0[kc + 8 * PLD]);
                ax[kt][2] = fu(ab0[kc + 4]);
                ax[kt][3] = fu(ab0[kc + 8 * PLD + 4]);
            }
            #pragma unroll
            for (int ni = 0; ni < 6; ++ni) {
                const int ntl = nh * 6 + ni;     // 0..11 within matrix
                const int jj0 = ntl * 8;
                float c[4] = {0.f, 0.f, 0.f, 0.f};
                const float2* wf = w_s + (ntl * 12) * 32 + lane;  // LDS.64 cf
                #pragma unroll
                for (int kt = 0; kt < 12; ++kt) {
                    float2 w = wf[kt * 32];
                    mma8(c, ax[kt][0], ax[kt][1], ax[kt][2], ax[kt][3],
                         fu(w.x), fu(w.y));
                }
                const float bv0 = qkv_b[mat * C_DIM + jj0 + tig * 2];
                const float bv1 = qkv_b[mat * C_DIM + jj0 + tig * 2 + 1];
                const int r0 = mt * 16 + gid, r1 = r0 + 8;
                const int j0 = jj0 + tig * 2;
                if (mat == 0) {          // q: fold softmax scale here
                    q_s[r0 * SLD + j0]     = f2tff((c[0] + bv0) * scale);
                    q_s[r0 * SLD + j0 + 1] = f2tff((c[1] + bv1) * scale);
                    q_s[r1 * SLD + j0]     = f2tff((c[2] + bv0) * scale);
                    q_s[r1 * SLD + j0 + 1] = f2tff((c[3] + bv1) * scale);
                } else if (mat == 1) {
                    if (r0 < 104) {
                        k_s[r0 * SLD + j0]     = f2tff(c[0] + bv0);
                        k_s[r0 * SLD + j0 + 1] = f2tff(c[1] + bv1);
                    }
                    if (r1 < 104) {
                        k_s[r1 * SLD + j0]     = f2tff(c[2] + bv0);
                        k_s[r1 * SLD + j0 + 1] = f2tff(c[3] + bv1);
                    }
                } else {
                    const int h  = jj0 / HD;
                    const int d0 = (jj0 % HD) + tig * 2;
                    float* vb = vT + h * (HD * VLD);
                    if (r0 < 104) {
                        vb[d0 * VLD + r0]       = f2tff(c[0] + bv0);
                        vb[(d0 + 1) * VLD + r0] = f2tff(c[1] + bv1);
                    }
                    if (r1 < 104) {
                        vb[d0 * VLD + r1]       = f2tff(c[2] + bv0);
                        vb[(d0 + 1) * VLD + r1] = f2tff(c[3] + bv1);
                    }
                }
            }
        }
        __syncthreads();   // w_s reused next mat; q/k/v ready after mat==2
    }

    // ---- Phase 2: fused attention, task=(head, m-tile), no smem round-trip -
    for (int t = warp; t < NHEAD * 7; t += NW) {
        const int h  = t / 7;
        const int mt = t % 7;
        const int hc = h * HD;
        const int r0 = mt * 16 + gid, r1 = r0 + 8;

        // cache q A-fragments (K=32 -> 4 k-tiles)
        uint32_t aq[4][4];
        {
            const float* ab0 = q_s + r0 * SLD + hc + tig;
            #pragma unroll
            for (int kt = 0; kt < 4; ++kt) {
                const int kc = kt * 8;
                aq[kt][0] = fu(ab0[kc]);
                aq[kt][1] = fu(ab0[kc + 8 * SLD]);
                aq[kt][2] = fu(ab0[kc + 4]);
                aq[kt][3] = fu(ab0[kc + 8 * SLD + 4]);
            }
        }

        // scores: 13 n-tiles in registers
        float c[13][4];
        #pragma unroll
        for (int nt = 0; nt < 13; ++nt) {
            c[nt][0] = c[nt][1] = c[nt][2] = c[nt][3] = 0.f;
            const float* bb = k_s + (nt * 8 + gid) * SLD + hc + tig;
            #pragma unroll
            for (int kt = 0; kt < 4; ++kt)
                mma8(c[nt], aq[kt][0], aq[kt][1], aq[kt][2], aq[kt][3],
                     fu(bb[kt * 8]), fu(bb[kt * 8 + 4]));
        }

        // bias (+column mask baked in) + row max
        const float4* bf = g_bias_f + ((h * 7 + mt) * 13) * 32 + lane;
        float mx0 = -1e30f, mx1 = -1e30f;
        #pragma unroll
        for (int nt = 0; nt < 13; ++nt) {
            float4 bv = bf[nt * 32];                  // coalesced LDG.128
            c[nt][0] += bv.x;
            c[nt][1] += bv.y;
            c[nt][2] += bv.z;
            c[nt][3] += bv.w;
            mx0 = fmaxf(mx0, fmaxf(c[nt][0], c[nt][1]));
            mx1 = fmaxf(mx1, fmaxf(c[nt][2], c[nt][3]));
        }
        // quad reduce (row owned by 4 consecutive lanes)
        mx0 = fmaxf(mx0, __shfl_xor_sync(0xffffffffu, mx0, 1));
        mx0 = fmaxf(mx0, __shfl_xor_sync(0xffffffffu, mx0, 2));
        mx1 = fmaxf(mx1, __shfl_xor_sync(0xffffffffu, mx1, 1));
        mx1 = fmaxf(mx1, __shfl_xor_sync(0xffffffffu, mx1, 2));

        float s0 = 0.f, s1 = 0.f;
        #pragma unroll
        for (int nt = 0; nt < 13; ++nt) {
            c[nt][0] = __expf(c[nt][0] - mx0);
            c[nt][1] = __expf(c[nt][1] - mx0);
            c[nt][2] = __expf(c[nt][2] - mx1);
            c[nt][3] = __expf(c[nt][3] - mx1);
            s0 += c[nt][0] + c[nt][1];
            s1 += c[nt][2] + c[nt][3];
        }
        s0 += __shfl_xor_sync(0xffffffffu, s0, 1);
        s0 += __shfl_xor_sync(0xffffffffu, s0, 2);
        s1 += __shfl_xor_sync(0xffffffffu, s1, 1);
        s1 += __shfl_xor_sync(0xffffffffu, s1, 2);
        const float inv0 = 1.0f / s0, inv1 = 1.0f / s1;

        // normalize + shuffle-transpose C-frag -> A-frag (tf32 bits)
        const int slot = tig & 1;
        const int sl0  = tig >> 1;        // src lane (in quad) for col tig
        const int sl1  = 2 + (tig >> 1);  // src lane for col tig+4
        #pragma unroll
        for (int nt = 0; nt < 13; ++nt) {
            float p0 = c[nt][0] * inv0;
            float p1 = c[nt][1] * inv0;
            float p2 = c[nt][2] * inv1;
            float p3 = c[nt][3] * inv1;
            float v00 = __shfl_sync(0xffffffffu, p0, sl0, 4);
            float v01 = __shfl_sync(0xffffffffu, p1, sl0, 4);
            float v20 = __shfl_sync(0xffffffffu, p0, sl1, 4);
            float v21 = __shfl_sync(0xffffffffu, p1, sl1, 4);
            float v10 = __shfl_sync(0xffffffffu, p2, sl0, 4);
            float v11 = __shfl_sync(0xffffffffu, p3, sl0, 4);
            float v30 = __shfl_sync(0xffffffffu, p2, sl1, 4);
            float v31 = __shfl_sync(0xffffffffu, p3, sl1, 4);
            c[nt][0] = __uint_as_float(f2tf(slot ? v01 : v00));  // (r_gid, tig)
            c[nt][1] = __uint_as_float(f2tf(slot ? v11 : v10));  // (r_gid+8, tig)
            c[nt][2] = __uint_as_float(f2tf(slot ? v21 : v20));  // (r_gid, tig+4)
            c[nt][3] = __uint_as_float(f2tf(slot ? v31 : v30));  // (r_gid+8, tig+4)
        }

        // AV: y[16,32] = P[16,104] @ V[104,32], A from registers
        float acc[4][4];
        #pragma unroll
        for (int ni = 0; ni < 4; ++ni) acc[ni][0]=acc[ni][1]=acc[ni][2]=acc[ni][3]=0.f;
        #pragma unroll
        for (int kt = 0; kt < 13; ++kt) {
            #pragma unroll
            for (int ni = 0; ni < 4; ++ni) {
                const float* bb = vT + h * (HD * VLD) + (ni * 8 + gid) * VLD + tig;
                mma8(acc[ni], fu(c[kt][0]), fu(c[kt][1]), fu(c[kt][2]), fu(c[kt][3]),
                     fu(bb[kt * 8]), fu(bb[kt * 8 + 4]));
            }
        }
        // write y back into this task's private q_s slice (tf32-rounded)
        #pragma unroll
        for (int ni = 0; ni < 4; ++ni) {
            const int cc = hc + ni * 8 + tig * 2;
            q_s[r0 * SLD + cc]     = f2tff(acc[ni][0]);
            q_s[r0 * SLD + cc + 1] = f2tff(acc[ni][1]);
            q_s[r1 * SLD + cc]     = f2tff(acc[ni][2]);
            q_s[r1 * SLD + cc + 1] = f2tff(acc[ni][3]);
        }
    }
    __syncthreads();

    // ---- Phase 3: proj [112,96]x[96,96] + bias, weights staged in SMEM -----
    {
        for (int i = tid; i < 12 * 12 * 32; i += NTHREADS)
            w_s[i] = g_proj_wf[i];
    }
    __syncthreads();

    float* ob = out + (size_t)b * (N_TOK * C_DIM);
    for (int t = warp; t < 14; t += NW) {
        const int mt = t >> 1;
        const int nh = t & 1;
        // cache A fragments (y) for this m-tile
        uint32_t ax[12][4];
        const float* ab0 = q_s + (mt * 16 + gid) * SLD + tig;
        #pragma unroll
        for (int kt = 0; kt < 12; ++kt) {
            const int kc = kt * 8;
            ax[kt][0] = fu(ab0[kc]);
            ax[kt][1] = fu(ab0[kc + 8 * SLD]);
            ax[kt][2] = fu(ab0[kc + 4]);
            ax[kt][3] = fu(ab0[kc + 8 * SLD + 4]);
        }
        const int r0 = mt * 16 + gid;
        #pragma unroll
        for (int ni = 0; ni < 6; ++ni) {
            const int nt = nh * 6 + ni;
            float c[4] = {0.f, 0.f, 0.f, 0.f};
            const float2* wf = w_s + (nt * 12) * 32 + lane;
            #pragma unroll
            for (int kt = 0; kt < 12; ++kt) {
                float2 w = wf[kt * 32];
                mma8(c, ax[kt][0], ax[kt][1], ax[kt][2], ax[kt][3],
                     fu(w.x), fu(w.y));
            }
            const int cc = nt * 8 + tig * 2;
            const float pb0 = proj_b[cc], pb1 = proj_b[cc + 1];
            if (r0 < N_TOK) {
                ob[r0 * C_DIM + cc]     = c[0] + pb0;
                ob[r0 * C_DIM + cc + 1] = c[1] + pb1;
            }
            if (r0 + 8 < N_TOK) {
                ob[(r0 + 8) * C_DIM + cc]     = c[2] + pb0;
                ob[(r0 + 8) * C_DIM + cc + 1] = c[3] + pb1;
            }
        }
    }
}

extern "C" void kernel_launch(void* const* d_in, const int* in_sizes, int n_in,
                              void* d_out, int out_size) {
    const float* x      = (const float*)d_in[0];
    const float* qkv_w  = (const float*)d_in[1];
    const float* qkv_b  = (const float*)d_in[2];
    const float* proj_w = (const float*)d_in[3];
    const float* proj_b = (const float*)d_in[4];
    const float* table  = (const float*)d_in[5];
    const int*   ridx   = (const int*)d_in[6];
    float* out = (float*)d_out;

    const int wprep = (36 + 12) * 12 * 32;
    weight_prep_kernel<<<(wprep + 255) / 256, 256>>>(qkv_w, proj_w);
    const int bprep = NHEAD * 7 * 13 * 32;
    bias_prep_kernel<<<(bprep + 255) / 256, 256>>>(table, ridx);

    cudaFuncSetAttribute(win_attn_kernel,
                         cudaFuncAttributeMaxDynamicSharedMemorySize, SMEM_BYTES);
    win_attn_kernel<<<NWIN, NTHREADS, SMEM_BYTES>>>(x, qkv_b, proj_b, out);
}

// round 15
// speedup vs baseline: 1.5894x; 1.5894x over previous
#include <cuda_runtime.h>
#include <cstdint>

// WindowAttention3D fused TF32 mma.sync kernel (one CTA per window).
// B=4096 windows, N=98 tokens (pad 112), C=96, H=3 heads, hd=32.
// R15: R12 structure (no weight staging — R13 regression reverted) with
// 672 threads / 21 warps so every phase's task count divides NW exactly:
// phase1 42/21=2, phase2 21/21=1, phase3 42/21=2 rounds, no idle tails.

#define N_TOK 98
#define C_DIM 96
#define NHEAD 3
#define HD    32
#define NWIN  4096
#define MPAD  112          // 7 x m16 tiles
#define SLD   100          // q_s / k_s row stride
#define PLD   108          // P (x) row stride
#define VLD   108          // vT row stride

#define NTHREADS 672
#define NW       21

// SMEM float offsets
#define Q_OFF 0                          // 112*100 = 11200   (q, later y)
#define K_OFF 11200                      // 104*100 = 10400
#define V_OFF 21600                      // 3*32*108 = 10368  (vT[h][d][token])
#define P_OFF 31968                      // 112*108 = 12096   (x)
#define SMEM_FLOATS 44064
#define SMEM_BYTES  (SMEM_FLOATS * 4)    // 176256 B

// Fragment-order operand caches (prep kernels fill; L2-resident).
// qkv weight B-frags: [nt=36][kt=12][lane=32] {w[n0+gid][kt8+tig], w[..][+4]}
__device__ float2 g_qkv_wf[36 * 12 * 32];
// proj weight B-frags: [nt=12][kt=12][lane=32]
__device__ float2 g_proj_wf[12 * 12 * 32];
// bias C-frags with column mask: [h=3][mt=7][nt=13][lane=32]
__device__ float4 g_bias_f[NHEAD * 7 * 13 * 32];

__device__ __forceinline__ uint32_t f2tf(float f) {
    uint32_t r;
    asm("cvt.rna.tf32.f32 %0, %1;" : "=r"(r) : "f"(f));
    return r;
}
__device__ __forceinline__ float f2tff(float f) { return __uint_as_float(f2tf(f)); }
__device__ __forceinline__ uint32_t fu(float f) { return __float_as_uint(f); }

__global__ void weight_prep_kernel(const float* __restrict__ qkv_w,
                                   const float* __restrict__ proj_w) {
    int i = blockIdx.x * blockDim.x + threadIdx.x;
    const int QKV_N = 36 * 12 * 32;
    if (i < QKV_N) {
        int lane = i & 31, kt = (i >> 5) % 12, nt = i / (32 * 12);
        int gid = lane >> 2, tig = lane & 3;
        int row = nt * 8 + gid, k = kt * 8 + tig;
        g_qkv_wf[i] = make_float2(f2tff(qkv_w[row * C_DIM + k]),
                                  f2tff(qkv_w[row * C_DIM + k + 4]));
    } else if (i < QKV_N + 12 * 12 * 32) {
        int j = i - QKV_N;
        int lane = j & 31, kt = (j >> 5) % 12, nt = j / (32 * 12);
        int gid = lane >> 2, tig = lane & 3;
        int row = nt * 8 + gid, k = kt * 8 + tig;
        g_proj_wf[j] = make_float2(f2tff(proj_w[row * C_DIM + k]),
                                   f2tff(proj_w[row * C_DIM + k + 4]));
    }
}

__global__ void bias_prep_kernel(const float* __restrict__ table,
                                 const int* __restrict__ ridx) {
    int i = blockIdx.x * blockDim.x + threadIdx.x;
    if (i < NHEAD * 7 * 13 * 32) {
        int lane = i & 31;
        int nt   = (i >> 5) % 13;
        int mt   = (i / (32 * 13)) % 7;
        int h    = i / (32 * 13 * 7);
        int gid = lane >> 2, tig = lane & 3;
        int r0 = mt * 16 + gid, r1 = r0 + 8;
        int c0 = nt * 8 + tig * 2;
        auto bv = [&](int r, int c) -> float {
            if (c >= N_TOK) return -1e30f;                    // column mask
            if (r >= N_TOK) return 0.f;                       // padded row
            return table[ridx[r * N_TOK + c] * NHEAD + h];
        };
        g_bias_f[i] = make_float4(bv(r0, c0), bv(r0, c0 + 1),
                                  bv(r1, c0), bv(r1, c0 + 1));
    }
}

__device__ __forceinline__ void mma8(float c[4],
                                     uint32_t a0, uint32_t a1, uint32_t a2, uint32_t a3,
                                     uint32_t b0, uint32_t b1) {
    asm volatile(
        "mma.sync.aligned.m16n8k8.row.col.f32.tf32.tf32.f32 "
        "{%0,%1,%2,%3}, {%4,%5,%6,%7}, {%8,%9}, {%0,%1,%2,%3};"
        : "+f"(c[0]), "+f"(c[1]), "+f"(c[2]), "+f"(c[3])
        : "r"(a0), "r"(a1), "r"(a2), "r"(a3), "r"(b0), "r"(b1));
}

__global__ void __launch_bounds__(NTHREADS, 1)
win_attn_kernel(const float* __restrict__ x,
                const float* __restrict__ qkv_b,   // [288]
                const float* __restrict__ proj_b,  // [96]
                float* __restrict__ out) {
    extern __shared__ float sm[];
    float* q_s = sm + Q_OFF;   // [112][SLD] q*scale, later y (per-(h,mt) private)
    float* k_s = sm + K_OFF;   // [104][SLD] k
    float* vT  = sm + V_OFF;   // [3][32][VLD] v transposed: [h][d][token]
    float* P   = sm + P_OFF;   // [112][PLD] x (TF32-rounded)

    const int tid  = threadIdx.x;
    const int lane = tid & 31;
    const int warp = tid >> 5;
    const int gid  = lane >> 2;   // groupID 0..7
    const int tig  = lane & 3;    // thread-in-group 0..3
    const int b    = blockIdx.x;
    const float* xb = x + (size_t)b * (N_TOK * C_DIM);

    // ---- Phase 0: load x -> P (TF32-rounded, float4), zero pad rows --------
    for (int i = tid * 4; i < N_TOK * C_DIM; i += NTHREADS * 4) {
        float4 v = *(const float4*)(xb + i);
        int n = i / C_DIM, c = i % C_DIM;
        float4 r = make_float4(f2tff(v.x), f2tff(v.y), f2tff(v.z), f2tff(v.w));
        *(float4*)(P + n * PLD + c) = r;
    }
    for (int i = tid; i < (MPAD - N_TOK) * C_DIM; i += NTHREADS) {
        int n = N_TOK + i / C_DIM, c = i % C_DIM;
        P[n * PLD + c] = 0.f;
    }
    __syncthreads();

    const float scale = 0.17677669529663687f;   // 32^-0.5

    // ---- Phase 1: QKV GEMM [112,96]x[96,288]; task=(m-tile, 6-col group) ---
    // 42 tasks over 21 warps = exactly 2 rounds.
    for (int t = warp; t < 42; t += NW) {
        const int mt = t / 6;
        const int ng = t % 6;
        // cache A fragments for this m-tile (x)
        uint32_t ax[12][4];
        const float* ab0 = P + (mt * 16 + gid) * PLD + tig;
        #pragma unroll
        for (int kt = 0; kt < 12; ++kt) {
            const int kc = kt * 8;
            ax[kt][0] = fu(ab0[kc]);
            ax[kt][1] = fu(ab0[kc + 8 * PLD]);
            ax[kt][2] = fu(ab0[kc + 4]);
            ax[kt][3] = fu(ab0[kc + 8 * PLD + 4]);
        }
        #pragma unroll
        for (int ni = 0; ni < 6; ++ni) {
            const int nt = ng * 6 + ni;
            const int n0 = nt * 8;
            const int mat = n0 / C_DIM;          // 0=q 1=k 2=v
            const int jj0 = n0 % C_DIM;
            float c[4] = {0.f, 0.f, 0.f, 0.f};
            const float2* wf = g_qkv_wf + (nt * 12) * 32 + lane;  // coalesced
            #pragma unroll
            for (int kt = 0; kt < 12; ++kt) {
                float2 w = wf[kt * 32];
                mma8(c, ax[kt][0], ax[kt][1], ax[kt][2], ax[kt][3],
                     fu(w.x), fu(w.y));
            }
            const float bv0 = qkv_b[n0 + tig * 2];
            const float bv1 = qkv_b[n0 + tig * 2 + 1];
            const int r0 = mt * 16 + gid, r1 = r0 + 8;
            const int j0 = jj0 + tig * 2;
            if (mat == 0) {          // q: fold softmax scale here
                q_s[r0 * SLD + j0]     = f2tff((c[0] + bv0) * scale);
                q_s[r0 * SLD + j0 + 1] = f2tff((c[1] + bv1) * scale);
                q_s[r1 * SLD + j0]     = f2tff((c[2] + bv0) * scale);
                q_s[r1 * SLD + j0 + 1] = f2tff((c[3] + bv1) * scale);
            } else if (mat == 1) {
                if (r0 < 104) {
                    k_s[r0 * SLD + j0]     = f2tff(c[0] + bv0);
                    k_s[r0 * SLD + j0 + 1] = f2tff(c[1] + bv1);
                }
                if (r1 < 104) {
                    k_s[r1 * SLD + j0]     = f2tff(c[2] + bv0);
                    k_s[r1 * SLD + j0 + 1] = f2tff(c[3] + bv1);
                }
            } else {
                const int h  = jj0 / HD;
                const int d0 = (jj0 % HD) + tig * 2;
                float* vb = vT + h * (HD * VLD);
                if (r0 < 104) {
                    vb[d0 * VLD + r0]       = f2tff(c[0] + bv0);
                    vb[(d0 + 1) * VLD + r0] = f2tff(c[1] + bv1);
                }
                if (r1 < 104) {
                    vb[d0 * VLD + r1]       = f2tff(c[2] + bv0);
                    vb[(d0 + 1) * VLD + r1] = f2tff(c[3] + bv1);
                }
            }
        }
    }
    __syncthreads();

    // ---- Phase 2: fused attention, task=(head, m-tile) ----------------------
    // 21 tasks over 21 warps = exactly 1 round; per-task-private q_s slice.
    for (int t = warp; t < NHEAD * 7; t += NW) {
        const int h  = t / 7;
        const int mt = t % 7;
        const int hc = h * HD;
        const int r0 = mt * 16 + gid, r1 = r0 + 8;

        // cache q A-fragments (K=32 -> 4 k-tiles)
        uint32_t aq[4][4];
        {
            const float* ab0 = q_s + r0 * SLD + hc + tig;
            #pragma unroll
            for (int kt = 0; kt < 4; ++kt) {
                const int kc = kt * 8;
                aq[kt][0] = fu(ab0[kc]);
                aq[kt][1] = fu(ab0[kc + 8 * SLD]);
                aq[kt][2] = fu(ab0[kc + 4]);
                aq[kt][3] = fu(ab0[kc + 8 * SLD + 4]);
            }
        }

        // scores: 13 n-tiles in registers
        float c[13][4];
        #pragma unroll
        for (int nt = 0; nt < 13; ++nt) {
            c[nt][0] = c[nt][1] = c[nt][2] = c[nt][3] = 0.f;
            const float* bb = k_s + (nt * 8 + gid) * SLD + hc + tig;
            #pragma unroll
            for (int kt = 0; kt < 4; ++kt)
                mma8(c[nt], aq[kt][0], aq[kt][1], aq[kt][2], aq[kt][3],
                     fu(bb[kt * 8]), fu(bb[kt * 8 + 4]));
        }

        // bias (+column mask baked in) + row max
        const float4* bf = g_bias_f + ((h * 7 + mt) * 13) * 32 + lane;
        float mx0 = -1e30f, mx1 = -1e30f;
        #pragma unroll
        for (int nt = 0; nt < 13; ++nt) {
            float4 bv = bf[nt * 32];                  // coalesced LDG.128
            c[nt][0] += bv.x;
            c[nt][1] += bv.y;
            c[nt][2] += bv.z;
            c[nt][3] += bv.w;
            mx0 = fmaxf(mx0, fmaxf(c[nt][0], c[nt][1]));
            mx1 = fmaxf(mx1, fmaxf(c[nt][2], c[nt][3]));
        }
        // quad reduce (row owned by 4 consecutive lanes)
        mx0 = fmaxf(mx0, __shfl_xor_sync(0xffffffffu, mx0, 1));
        mx0 = fmaxf(mx0, __shfl_xor_sync(0xffffffffu, mx0, 2));
        mx1 = fmaxf(mx1, __shfl_xor_sync(0xffffffffu, mx1, 1));
        mx1 = fmaxf(mx1, __shfl_xor_sync(0xffffffffu, mx1, 2));

        float s0 = 0.f, s1 = 0.f;
        #pragma unroll
        for (int nt = 0; nt < 13; ++nt) {
            c[nt][0] = __expf(c[nt][0] - mx0);
            c[nt][1] = __expf(c[nt][1] - mx0);
            c[nt][2] = __expf(c[nt][2] - mx1);
            c[nt][3] = __expf(c[nt][3] - mx1);
            s0 += c[nt][0] + c[nt][1];
            s1 += c[nt][2] + c[nt][3];
        }
        s0 += __shfl_xor_sync(0xffffffffu, s0, 1);
        s0 += __shfl_xor_sync(0xffffffffu, s0, 2);
        s1 += __shfl_xor_sync(0xffffffffu, s1, 1);
        s1 += __shfl_xor_sync(0xffffffffu, s1, 2);
        const float inv0 = 1.0f / s0, inv1 = 1.0f / s1;

        // normalize + shuffle-transpose C-frag -> A-frag (tf32 bits)
        const int slot = tig & 1;
        const int sl0  = tig >> 1;        // src lane (in quad) for col tig
        const int sl1  = 2 + (tig >> 1);  // src lane for col tig+4
        #pragma unroll
        for (int nt = 0; nt < 13; ++nt) {
            float p0 = c[nt][0] * inv0;
            float p1 = c[nt][1] * inv0;
            float p2 = c[nt][2] * inv1;
            float p3 = c[nt][3] * inv1;
            float v00 = __shfl_sync(0xffffffffu, p0, sl0, 4);
            float v01 = __shfl_sync(0xffffffffu, p1, sl0, 4);
            float v20 = __shfl_sync(0xffffffffu, p0, sl1, 4);
            float v21 = __shfl_sync(0xffffffffu, p1, sl1, 4);
            float v10 = __shfl_sync(0xffffffffu, p2, sl0, 4);
            float v11 = __shfl_sync(0xffffffffu, p3, sl0, 4);
            float v30 = __shfl_sync(0xffffffffu, p2, sl1, 4);
            float v31 = __shfl_sync(0xffffffffu, p3, sl1, 4);
            c[nt][0] = __uint_as_float(f2tf(slot ? v01 : v00));  // (r_gid, tig)
            c[nt][1] = __uint_as_float(f2tf(slot ? v11 : v10));  // (r_gid+8, tig)
            c[nt][2] = __uint_as_float(f2tf(slot ? v21 : v20));  // (r_gid, tig+4)
            c[nt][3] = __uint_as_float(f2tf(slot ? v31 : v30));  // (r_gid+8, tig+4)
        }

        // AV: y[16,32] = P[16,104] @ V[104,32], A from registers
        float acc[4][4];
        #pragma unroll
        for (int ni = 0; ni < 4; ++ni) acc[ni][0]=acc[ni][1]=acc[ni][2]=acc[ni][3]=0.f;
        #pragma unroll
        for (int kt = 0; kt < 13; ++kt) {
            #pragma unroll
            for (int ni = 0; ni < 4; ++ni) {
                const float* bb = vT + h * (HD * VLD) + (ni * 8 + gid) * VLD + tig;
                mma8(acc[ni], fu(c[kt][0]), fu(c[kt][1]), fu(c[kt][2]), fu(c[kt][3]),
                     fu(bb[kt * 8]), fu(bb[kt * 8 + 4]));
            }
        }
        // write y back into this task's private q_s slice (tf32-rounded)
        #pragma unroll
        for (int ni = 0; ni < 4; ++ni) {
            const int cc = hc + ni * 8 + tig * 2;
            q_s[r0 * SLD + cc]     = f2tff(acc[ni][0]);
            q_s[r0 * SLD + cc + 1] = f2tff(acc[ni][1]);
            q_s[r1 * SLD + cc]     = f2tff(acc[ni][2]);
            q_s[r1 * SLD + cc + 1] = f2tff(acc[ni][3]);
        }
    }
    __syncthreads();

    // ---- Phase 3: proj [112,96]x[96,96] + bias; task=(m-tile, n-pair) ------
    // 42 tasks over 21 warps = exactly 2 rounds.
    float* ob = out + (size_t)b * (N_TOK * C_DIM);
    for (int t = warp; t < 42; t += NW) {
        const int mt = t / 6, ntp = t % 6;
        float c[2][4];
        #pragma unroll
        for (int ni = 0; ni < 2; ++ni) { c[ni][0]=c[ni][1]=c[ni][2]=c[ni][3]=0.f; }
        const float* ab0 = q_s + (mt * 16 + gid) * SLD + tig;
        const float2* wf0 = g_proj_wf + ((ntp * 2) * 12) * 32 + lane;
        const float2* wf1 = g_proj_wf + ((ntp * 2 + 1) * 12) * 32 + lane;
        #pragma unroll
        for (int kt = 0; kt < 12; ++kt) {
            const int kc = kt * 8;
            uint32_t a0 = fu(ab0[kc]);
            uint32_t a1 = fu(ab0[kc + 8 * SLD]);
            uint32_t a2 = fu(ab0[kc + 4]);
            uint32_t a3 = fu(ab0[kc + 8 * SLD + 4]);
            float2 w0 = wf0[kt * 32];
            float2 w1 = wf1[kt * 32];
            mma8(c[0], a0, a1, a2, a3, fu(w0.x), fu(w0.y));
            mma8(c[1], a0, a1, a2, a3, fu(w1.x), fu(w1.y));
        }
        const int r0 = mt * 16 + gid;
        #pragma unroll
        for (int ni = 0; ni < 2; ++ni) {
            const int nt = ntp * 2 + ni;
            const int cc = nt * 8 + tig * 2;
            const float pb0 = proj_b[cc], pb1 = proj_b[cc + 1];
            if (r0 < N_TOK) {
                ob[r0 * C_DIM + cc]     = c[ni][0] + pb0;
                ob[r0 * C_DIM + cc + 1] = c[ni][1] + pb1;
            }
            if (r0 + 8 < N_TOK) {
                ob[(r0 + 8) * C_DIM + cc]     = c[ni][2] + pb0;
                ob[(r0 + 8) * C_DIM + cc + 1] = c[ni][3] + pb1;
            }
        }
    }
}

extern "C" void kernel_launch(void* const* d_in, const int* in_sizes, int n_in,
                              void* d_out, int out_size) {
    const float* x      = (const float*)d_in[0];
    const float* qkv_w  = (const float*)d_in[1];
    const float* qkv_b  = (const float*)d_in[2];
    const float* proj_w = (const float*)d_in[3];
    const float* proj_b = (const float*)d_in[4];
    const float* table  = (const float*)d_in[5];
    const int*   ridx   = (const int*)d_in[6];
    float* out = (float*)d_out;

    const int wprep = (36 + 12) * 12 * 32;
    weight_prep_kernel<<<(wprep + 255) / 256, 256>>>(qkv_w, proj_w);
    const int bprep = NHEAD * 7 * 13 * 32;
    bias_prep_kernel<<<(bprep + 255) / 256, 256>>>(table, ridx);

    cudaFuncSetAttribute(win_attn_kernel,
                         cudaFuncAttributeMaxDynamicSharedMemorySize, SMEM_BYTES);
    win_attn_kernel<<<NWIN, NTHREADS, SMEM_BYTES>>>(x, qkv_b, proj_b, out);
}

// round 16
// speedup vs baseline: 1.6313x; 1.0264x over previous
#include <cuda_runtime.h>
#include <cstdint>

// WindowAttention3D fused TF32 mma.sync kernel (one CTA per window).
// B=4096 windows, N=98 tokens (pad 112), C=96, H=3 heads, hd=32.
// R16: MMA dependency chains broken by loop interleave — independent
// accumulators innermost in QKV / scores / proj (AV already was).
// Keeps R15 geometry: 672 threads / 21 warps, fragment-order operands.

#define N_TOK 98
#define C_DIM 96
#define NHEAD 3
#define HD    32
#define NWIN  4096
#define MPAD  112          // 7 x m16 tiles
#define SLD   100          // q_s / k_s row stride
#define PLD   108          // P (x) row stride
#define VLD   108          // vT row stride

#define NTHREADS 672
#define NW       21

// SMEM float offsets
#define Q_OFF 0                          // 112*100 = 11200   (q, later y)
#define K_OFF 11200                      // 104*100 = 10400
#define V_OFF 21600                      // 3*32*108 = 10368  (vT[h][d][token])
#define P_OFF 31968                      // 112*108 = 12096   (x)
#define SMEM_FLOATS 44064
#define SMEM_BYTES  (SMEM_FLOATS * 4)    // 176256 B

// Fragment-order operand caches (prep kernels fill; L2-resident).
__device__ float2 g_qkv_wf[36 * 12 * 32];
__device__ float2 g_proj_wf[12 * 12 * 32];
__device__ float4 g_bias_f[NHEAD * 7 * 13 * 32];

__device__ __forceinline__ uint32_t f2tf(float f) {
    uint32_t r;
    asm("cvt.rna.tf32.f32 %0, %1;" : "=r"(r) : "f"(f));
    return r;
}
__device__ __forceinline__ float f2tff(float f) { return __uint_as_float(f2tf(f)); }
__device__ __forceinline__ uint32_t fu(float f) { return __float_as_uint(f); }

__global__ void weight_prep_kernel(const float* __restrict__ qkv_w,
                                   const float* __restrict__ proj_w) {
    int i = blockIdx.x * blockDim.x + threadIdx.x;
    const int QKV_N = 36 * 12 * 32;
    if (i < QKV_N) {
        int lane = i & 31, kt = (i >> 5) % 12, nt = i / (32 * 12);
        int gid = lane >> 2, tig = lane & 3;
        int row = nt * 8 + gid, k = kt * 8 + tig;
        g_qkv_wf[i] = make_float2(f2tff(qkv_w[row * C_DIM + k]),
                                  f2tff(qkv_w[row * C_DIM + k + 4]));
    } else if (i < QKV_N + 12 * 12 * 32) {
        int j = i - QKV_N;
        int lane = j & 31, kt = (j >> 5) % 12, nt = j / (32 * 12);
        int gid = lane >> 2, tig = lane & 3;
        int row = nt * 8 + gid, k = kt * 8 + tig;
        g_proj_wf[j] = make_float2(f2tff(proj_w[row * C_DIM + k]),
                                   f2tff(proj_w[row * C_DIM + k + 4]));
    }
}

__global__ void bias_prep_kernel(const float* __restrict__ table,
                                 const int* __restrict__ ridx) {
    int i = blockIdx.x * blockDim.x + threadIdx.x;
    if (i < NHEAD * 7 * 13 * 32) {
        int lane = i & 31;
        int nt   = (i >> 5) % 13;
        int mt   = (i / (32 * 13)) % 7;
        int h    = i / (32 * 13 * 7);
        int gid = lane >> 2, tig = lane & 3;
        int r0 = mt * 16 + gid, r1 = r0 + 8;
        int c0 = nt * 8 + tig * 2;
        auto bv = [&](int r, int c) -> float {
            if (c >= N_TOK) return -1e30f;                    // column mask
            if (r >= N_TOK) return 0.f;                       // padded row
            return table[ridx[r * N_TOK + c] * NHEAD + h];
        };
        g_bias_f[i] = make_float4(bv(r0, c0), bv(r0, c0 + 1),
                                  bv(r1, c0), bv(r1, c0 + 1));
    }
}

__device__ __forceinline__ void mma8(float c[4],
                                     uint32_t a0, uint32_t a1, uint32_t a2, uint32_t a3,
                                     uint32_t b0, uint32_t b1) {
    asm volatile(
        "mma.sync.aligned.m16n8k8.row.col.f32.tf32.tf32.f32 "
        "{%0,%1,%2,%3}, {%4,%5,%6,%7}, {%8,%9}, {%0,%1,%2,%3};"
        : "+f"(c[0]), "+f"(c[1]), "+f"(c[2]), "+f"(c[3])
        : "r"(a0), "r"(a1), "r"(a2), "r"(a3), "r"(b0), "r"(b1));
}

__global__ void __launch_bounds__(NTHREADS, 1)
win_attn_kernel(const float* __restrict__ x,
                const float* __restrict__ qkv_b,   // [288]
                const float* __restrict__ proj_b,  // [96]
                float* __restrict__ out) {
    extern __shared__ float sm[];
    float* q_s = sm + Q_OFF;   // [112][SLD] q*scale, later y (per-(h,mt) private)
    float* k_s = sm + K_OFF;   // [104][SLD] k
    float* vT  = sm + V_OFF;   // [3][32][VLD] v transposed: [h][d][token]
    float* P   = sm + P_OFF;   // [112][PLD] x (TF32-rounded)

    const int tid  = threadIdx.x;
    const int lane = tid & 31;
    const int warp = tid >> 5;
    const int gid  = lane >> 2;   // groupID 0..7
    const int tig  = lane & 3;    // thread-in-group 0..3
    const int b    = blockIdx.x;
    const float* xb = x + (size_t)b * (N_TOK * C_DIM);

    // ---- Phase 0: load x -> P (TF32-rounded, float4), zero pad rows --------
    for (int i = tid * 4; i < N_TOK * C_DIM; i += NTHREADS * 4) {
        float4 v = *(const float4*)(xb + i);
        int n = i / C_DIM, c = i % C_DIM;
        float4 r = make_float4(f2tff(v.x), f2tff(v.y), f2tff(v.z), f2tff(v.w));
        *(float4*)(P + n * PLD + c) = r;
    }
    for (int i = tid; i < (MPAD - N_TOK) * C_DIM; i += NTHREADS) {
        int n = N_TOK + i / C_DIM, c = i % C_DIM;
        P[n * PLD + c] = 0.f;
    }
    __syncthreads();

    const float scale = 0.17677669529663687f;   // 32^-0.5

    // ---- Phase 1: QKV GEMM; task=(m-tile, 6-nt group), 42 tasks = 2 rounds -
    // Inner order: half(3 nt) -> kt -> ni, so 3 independent MMA chains
    // interleave (ILP=3) instead of one 12-deep dependent chain.
    for (int t = warp; t < 42; t += NW) {
        const int mt = t / 6;
        const int ng = t % 6;
        // cache A fragments for this m-tile (x)
        uint32_t ax[12][4];
        const float* ab0 = P + (mt * 16 + gid) * PLD + tig;
        #pragma unroll
        for (int kt = 0; kt < 12; ++kt) {
            const int kc = kt * 8;
            ax[kt][0] = fu(ab0[kc]);
            ax[kt][1] = fu(ab0[kc + 8 * PLD]);
            ax[kt][2] = fu(ab0[kc + 4]);
            ax[kt][3] = fu(ab0[kc + 8 * PLD + 4]);
        }
        #pragma unroll
        for (int half = 0; half < 2; ++half) {
            const int ntb = ng * 6 + half * 3;   // 3-tile block, mat-aligned
            float c[3][4];
            #pragma unroll
            for (int ni = 0; ni < 3; ++ni) { c[ni][0]=c[ni][1]=c[ni][2]=c[ni][3]=0.f; }
            #pragma unroll
            for (int kt = 0; kt < 12; ++kt) {
                #pragma unroll
                for (int ni = 0; ni < 3; ++ni) {
                    float2 w = g_qkv_wf[((ntb + ni) * 12 + kt) * 32 + lane];
                    mma8(c[ni], ax[kt][0], ax[kt][1], ax[kt][2], ax[kt][3],
                         fu(w.x), fu(w.y));
                }
            }
            #pragma unroll
            for (int ni = 0; ni < 3; ++ni) {
                const int nt = ntb + ni;
                const int n0 = nt * 8;
                const int mat = n0 / C_DIM;      // 0=q 1=k 2=v
                const int jj0 = n0 % C_DIM;
                const float bv0 = qkv_b[n0 + tig * 2];
                const float bv1 = qkv_b[n0 + tig * 2 + 1];
                const int r0 = mt * 16 + gid, r1 = r0 + 8;
                const int j0 = jj0 + tig * 2;
                if (mat == 0) {          // q: fold softmax scale here
                    q_s[r0 * SLD + j0]     = f2tff((c[ni][0] + bv0) * scale);
                    q_s[r0 * SLD + j0 + 1] = f2tff((c[ni][1] + bv1) * scale);
                    q_s[r1 * SLD + j0]     = f2tff((c[ni][2] + bv0) * scale);
                    q_s[r1 * SLD + j0 + 1] = f2tff((c[ni][3] + bv1) * scale);
                } else if (mat == 1) {
                    if (r0 < 104) {
                        k_s[r0 * SLD + j0]     = f2tff(c[ni][0] + bv0);
                        k_s[r0 * SLD + j0 + 1] = f2tff(c[ni][1] + bv1);
                    }
                    if (r1 < 104) {
                        k_s[r1 * SLD + j0]     = f2tff(c[ni][2] + bv0);
                        k_s[r1 * SLD + j0 + 1] = f2tff(c[ni][3] + bv1);
                    }
                } else {
                    const int h  = jj0 / HD;
                    const int d0 = (jj0 % HD) + tig * 2;
                    float* vb = vT + h * (HD * VLD);
                    if (r0 < 104) {
                        vb[d0 * VLD + r0]       = f2tff(c[ni][0] + bv0);
                        vb[(d0 + 1) * VLD + r0] = f2tff(c[ni][1] + bv1);
                    }
                    if (r1 < 104) {
                        vb[d0 * VLD + r1]       = f2tff(c[ni][2] + bv0);
                        vb[(d0 + 1) * VLD + r1] = f2tff(c[ni][3] + bv1);
                    }
                }
            }
        }
    }
    __syncthreads();

    // ---- Phase 2: fused attention, task=(head, m-tile), 21 tasks = 1 round -
    for (int t = warp; t < NHEAD * 7; t += NW) {
        const int h  = t / 7;
        const int mt = t % 7;
        const int hc = h * HD;
        const int r0 = mt * 16 + gid, r1 = r0 + 8;

        // cache q A-fragments (K=32 -> 4 k-tiles)
        uint32_t aq[4][4];
        {
            const float* ab0 = q_s + r0 * SLD + hc + tig;
            #pragma unroll
            for (int kt = 0; kt < 4; ++kt) {
                const int kc = kt * 8;
                aq[kt][0] = fu(ab0[kc]);
                aq[kt][1] = fu(ab0[kc + 8 * SLD]);
                aq[kt][2] = fu(ab0[kc + 4]);
                aq[kt][3] = fu(ab0[kc + 8 * SLD + 4]);
            }
        }

        // scores: kt outer, nt inner -> 13 independent chains (ILP=13)
        float c[13][4];
        #pragma unroll
        for (int nt = 0; nt < 13; ++nt) { c[nt][0]=c[nt][1]=c[nt][2]=c[nt][3]=0.f; }
        #pragma unroll
        for (int kt = 0; kt < 4; ++kt) {
            const int kc = kt * 8;
            #pragma unroll
            for (int nt = 0; nt < 13; ++nt) {
                const float* bb = k_s + (nt * 8 + gid) * SLD + hc + tig + kc;
                mma8(c[nt], aq[kt][0], aq[kt][1], aq[kt][2], aq[kt][3],
                     fu(bb[0]), fu(bb[4]));
            }
        }

        // bias (+column mask baked in) + row max
        const float4* bf = g_bias_f + ((h * 7 + mt) * 13) * 32 + lane;
        float mx0 = -1e30f, mx1 = -1e30f;
        #pragma unroll
        for (int nt = 0; nt < 13; ++nt) {
            float4 bv = bf[nt * 32];                  // coalesced LDG.128
            c[nt][0] += bv.x;
            c[nt][1] += bv.y;
            c[nt][2] += bv.z;
            c[nt][3] += bv.w;
            mx0 = fmaxf(mx0, fmaxf(c[nt][0], c[nt][1]));
            mx1 = fmaxf(mx1, fmaxf(c[nt][2], c[nt][3]));
        }
        // quad reduce (row owned by 4 consecutive lanes)
        mx0 = fmaxf(mx0, __shfl_xor_sync(0xffffffffu, mx0, 1));
        mx0 = fmaxf(mx0, __shfl_xor_sync(0xffffffffu, mx0, 2));
        mx1 = fmaxf(mx1, __shfl_xor_sync(0xffffffffu, mx1, 1));
        mx1 = fmaxf(mx1, __shfl_xor_sync(0xffffffffu, mx1, 2));

        float s0 = 0.f, s1 = 0.f;
        #pragma unroll
        for (int nt = 0; nt < 13; ++nt) {
            c[nt][0] = __expf(c[nt][0] - mx0);
            c[nt][1] = __expf(c[nt][1] - mx0);
            c[nt][2] = __expf(c[nt][2] - mx1);
            c[nt][3] = __expf(c[nt][3] - mx1);
            s0 += c[nt][0] + c[nt][1];
            s1 += c[nt][2] + c[nt][3];
        }
        s0 += __shfl_xor_sync(0xffffffffu, s0, 1);
        s0 += __shfl_xor_sync(0xffffffffu, s0, 2);
        s1 += __shfl_xor_sync(0xffffffffu, s1, 1);
        s1 += __shfl_xor_sync(0xffffffffu, s1, 2);
        const float inv0 = 1.0f / s0, inv1 = 1.0f / s1;

        // normalize + shuffle-transpose C-frag -> A-frag (tf32 bits)
        const int slot = tig & 1;
        const int sl0  = tig >> 1;        // src lane (in quad) for col tig
        const int sl1  = 2 + (tig >> 1);  // src lane for col tig+4
        #pragma unroll
        for (int nt = 0; nt < 13; ++nt) {
            float p0 = c[nt][0] * inv0;
            float p1 = c[nt][1] * inv0;
            float p2 = c[nt][2] * inv1;
            float p3 = c[nt][3] * inv1;
            float v00 = __shfl_sync(0xffffffffu, p0, sl0, 4);
            float v01 = __shfl_sync(0xffffffffu, p1, sl0, 4);
            float v20 = __shfl_sync(0xffffffffu, p0, sl1, 4);
            float v21 = __shfl_sync(0xffffffffu, p1, sl1, 4);
            float v10 = __shfl_sync(0xffffffffu, p2, sl0, 4);
            float v11 = __shfl_sync(0xffffffffu, p3, sl0, 4);
            float v30 = __shfl_sync(0xffffffffu, p2, sl1, 4);
            float v31 = __shfl_sync(0xffffffffu, p3, sl1, 4);
            c[nt][0] = __uint_as_float(f2tf(slot ? v01 : v00));  // (r_gid, tig)
            c[nt][1] = __uint_as_float(f2tf(slot ? v11 : v10));  // (r_gid+8, tig)
            c[nt][2] = __uint_as_float(f2tf(slot ? v21 : v20));  // (r_gid, tig+4)
            c[nt][3] = __uint_as_float(f2tf(slot ? v31 : v30));  // (r_gid+8, tig+4)
        }

        // AV: y[16,32] = P[16,104] @ V[104,32], A from registers (ILP=4 already)
        float acc[4][4];
        #pragma unroll
        for (int ni = 0; ni < 4; ++ni) acc[ni][0]=acc[ni][1]=acc[ni][2]=acc[ni][3]=0.f;
        #pragma unroll
        for (int kt = 0; kt < 13; ++kt) {
            #pragma unroll
            for (int ni = 0; ni < 4; ++ni) {
                const float* bb = vT + h * (HD * VLD) + (ni * 8 + gid) * VLD + tig;
                mma8(acc[ni], fu(c[kt][0]), fu(c[kt][1]), fu(c[kt][2]), fu(c[kt][3]),
                     fu(bb[kt * 8]), fu(bb[kt * 8 + 4]));
            }
        }
        // write y back into this task's private q_s slice (tf32-rounded)
        #pragma unroll
        for (int ni = 0; ni < 4; ++ni) {
            const int cc = hc + ni * 8 + tig * 2;
            q_s[r0 * SLD + cc]     = f2tff(acc[ni][0]);
            q_s[r0 * SLD + cc + 1] = f2tff(acc[ni][1]);
            q_s[r1 * SLD + cc]     = f2tff(acc[ni][2]);
            q_s[r1 * SLD + cc + 1] = f2tff(acc[ni][3]);
        }
    }
    __syncthreads();

    // ---- Phase 3: proj; task=(m-tile, n-third of 4 nt), 21 tasks = 1 round -
    // kt outer, ni inner -> 4 independent chains (ILP=4).
    float* ob = out + (size_t)b * (N_TOK * C_DIM);
    for (int t = warp; t < 21; t += NW) {
        const int mt = t / 3, ng = t % 3;
        // cache A fragments (y) for this m-tile
        uint32_t ax[12][4];
        const float* ab0 = q_s + (mt * 16 + gid) * SLD + tig;
        #pragma unroll
        for (int kt = 0; kt < 12; ++kt) {
            const int kc = kt * 8;
            ax[kt][0] = fu(ab0[kc]);
            ax[kt][1] = fu(ab0[kc + 8 * SLD]);
            ax[kt][2] = fu(ab0[kc + 4]);
            ax[kt][3] = fu(ab0[kc + 8 * SLD + 4]);
        }
        float c[4][4];
        #pragma unroll
        for (int ni = 0; ni < 4; ++ni) { c[ni][0]=c[ni][1]=c[ni][2]=c[ni][3]=0.f; }
        #pragma unroll
        for (int kt = 0; kt < 12; ++kt) {
            #pragma unroll
            for (int ni = 0; ni < 4; ++ni) {
                const int nt = ng * 4 + ni;
                float2 w = g_proj_wf[(nt * 12 + kt) * 32 + lane];
                mma8(c[ni], ax[kt][0], ax[kt][1], ax[kt][2], ax[kt][3],
                     fu(w.x), fu(w.y));
            }
        }
        const int r0 = mt * 16 + gid;
        #pragma unroll
        for (int ni = 0; ni < 4; ++ni) {
            const int nt = ng * 4 + ni;
            const int cc = nt * 8 + tig * 2;
            const float pb0 = proj_b[cc], pb1 = proj_b[cc + 1];
            if (r0 < N_TOK) {
                ob[r0 * C_DIM + cc]     = c[ni][0] + pb0;
                ob[r0 * C_DIM + cc + 1] = c[ni][1] + pb1;
            }
            if (r0 + 8 < N_TOK) {
                ob[(r0 + 8) * C_DIM + cc]     = c[ni][2] + pb0;
                ob[(r0 + 8) * C_DIM + cc + 1] = c[ni][3] + pb1;
            }
        }
    }
}

extern "C" void kernel_launch(void* const* d_in, const int* in_sizes, int n_in,
                              void* d_out, int out_size) {
    const float* x      = (const float*)d_in[0];
    const float* qkv_w  = (const float*)d_in[1];
    const float* qkv_b  = (const float*)d_in[2];
    const float* proj_w = (const float*)d_in[3];
    const float* proj_b = (const float*)d_in[4];
    const float* table  = (const float*)d_in[5];
    const int*   ridx   = (const int*)d_in[6];
    float* out = (float*)d_out;

    const int wprep = (36 + 12) * 12 * 32;
    weight_prep_kernel<<<(wprep + 255) / 256, 256>>>(qkv_w, proj_w);
    const int bprep = NHEAD * 7 * 13 * 32;
    bias_prep_kernel<<<(bprep + 255) / 256, 256>>>(table, ridx);

    cudaFuncSetAttribute(win_attn_kernel,
                         cudaFuncAttributeMaxDynamicSharedMemorySize, SMEM_BYTES);
    win_attn_kernel<<<NWIN, NTHREADS, SMEM_BYTES>>>(x, qkv_b, proj_b, out);
}